// round 3
// baseline (speedup 1.0000x reference)
#include <cuda_runtime.h>
#include <cstdint>

#define SEQ   2048
#define BATCH 128
#define INP   64
#define HID   256
#define GH    1024   // 4*HID
#define OUTD  64

typedef unsigned long long ull;

// packed 2xfp32 FMA (B300: FFMA-3reg is half rate; f32x2 restores full rate)
#define FMA2(d, a, b) asm("fma.rn.f32x2 %0, %1, %2, %0;" : "+l"(d) : "l"(a), "l"(b))

__device__ __forceinline__ float hsum2(ull v) {
    float2 f = *(float2*)&v;
    return f.x + f.y;
}
__device__ __forceinline__ ull pack2(float lo, float hi) {
    float2 f = make_float2(lo, hi);
    return *(ull*)&f;
}

// ---------------- scratch (static device arrays; no cudaMalloc) --------
__device__ float g_xw[(size_t)SEQ * BATCH * GH];   // x @ W_ih^T + b
__device__ float g_hs[(size_t)SEQ * BATCH * HID];  // h history

// =============================================================
// Kernel A (proven R1 form): xw[m][g] = sum_i x[m][i]*W_ih[g][i] + b[g]
// =============================================================
__global__ void __launch_bounds__(256) k_gemm_xw(const float* __restrict__ x,
                                                 const float* __restrict__ Wih,
                                                 const float* __restrict__ bias)
{
    extern __shared__ float4 smA[];
    float4* Xs = smA;            // 64 rows x 19
    float4* Ws = smA + 64 * 19;  // 128 rows x 19

    const int t  = threadIdx.x;
    const int m0 = blockIdx.x * 64;
    const int n0 = blockIdx.y * 128;

    const float4* x4 = (const float4*)x;
    const float4* w4 = (const float4*)Wih;

    #pragma unroll
    for (int idx = t; idx < 64 * 16; idx += 256) {
        int r = idx >> 4, c = idx & 15;
        Xs[r * 19 + c] = x4[(size_t)(m0 + r) * 16 + c];
    }
    #pragma unroll
    for (int idx = t; idx < 128 * 16; idx += 256) {
        int r = idx >> 4, c = idx & 15;
        Ws[r * 19 + c] = w4[(size_t)(n0 + r) * 16 + c];
    }
    __syncthreads();

    const int tx = t & 15, ty = t >> 4;
    float acc[4][8];
    #pragma unroll
    for (int i = 0; i < 4; i++)
        #pragma unroll
        for (int j = 0; j < 8; j++) acc[i][j] = 0.f;

    #pragma unroll
    for (int k4 = 0; k4 < 16; k4++) {
        float4 a[4], bv[8];
        #pragma unroll
        for (int i = 0; i < 4; i++) a[i] = Xs[(ty + 16 * i) * 19 + k4];
        #pragma unroll
        for (int j = 0; j < 8; j++) bv[j] = Ws[(tx + 16 * j) * 19 + k4];
        #pragma unroll
        for (int i = 0; i < 4; i++)
            #pragma unroll
            for (int j = 0; j < 8; j++)
                acc[i][j] += a[i].x * bv[j].x + a[i].y * bv[j].y +
                             a[i].z * bv[j].z + a[i].w * bv[j].w;
    }
    #pragma unroll
    for (int i = 0; i < 4; i++) {
        int m = m0 + ty + 16 * i;
        #pragma unroll
        for (int j = 0; j < 8; j++) {
            int n = n0 + tx + 16 * j;
            g_xw[(size_t)m * GH + n] = acc[i][j] + __ldg(&bias[n]);
        }
    }
}

// =============================================================
// Kernel B: persistent LSTM scan. 128 CTAs = 16 batch-groups(8 b) x
// 8 unit-groups(32 u). Cluster of 8 per batch-group; h via DSMEM.
// W_hh lives in REGISTERS (thread = (gate row, K-slice of 64)).
// One cluster barrier per step (double-buffered h publish).
// =============================================================
#define HSK 516   // float stride between ks-slices in Hsm (banks 0/4/8/12)
#define LST 132   // float stride between batches in Lsm

__global__ void __launch_bounds__(512, 1) __cluster_dims__(8, 1, 1)
k_lstm(const float* __restrict__ h0, const float* __restrict__ c0,
       const float* __restrict__ Whh)
{
    __shared__ float Hsm[4 * HSK];      // h_prev: [ks][b*64 + off]
    __shared__ float Lsm[8 * LST];      // lin results: [b][row]
    __shared__ float Hnew[2 * 256];     // published h slice, x2 parity

    const int t      = threadIdx.x;
    const int bgrp   = blockIdx.x >> 3;     // 0..15
    const int myrank = blockIdx.x & 7;      // cluster rank
    const int b0g    = bgrp << 3;           // global batch base (8 batches)
    const int u0     = myrank << 5;         // global unit base (32 units)

    // GEMV mapping: r = gate row 0..127, ks = K-slice 0..3 (adjacent lanes)
    const int r  = t >> 2;
    const int ks = t & 3;
    const int grow = ((r >> 5) << 8) + u0 + (r & 31);   // global gate row

    // ---- W_hh slice into registers (64 floats = 32 ull), once ----
    ull w[32];
    {
        const float4* wg = (const float4*)(Whh + (size_t)grow * HID + ks * 64);
        #pragma unroll
        for (int i = 0; i < 16; i++) {
            float4 v = wg[i];
            w[2 * i]     = pack2(v.x, v.y);
            w[2 * i + 1] = pack2(v.z, v.w);
        }
    }

    // ---- init Hsm from h0 ----
    {
        int b = t >> 6, c4 = t & 63;            // 512 threads -> 8b x 64 f4
        float4 v = ((const float4*)h0)[(size_t)(b0g + b) * 64 + c4];
        int ksd = c4 >> 4, off = (c4 & 15) << 2;
        *(float4*)(Hsm + ksd * HSK + b * 64 + off) = v;
    }

    // ---- gate-thread state in registers (t < 256: b = t>>5, u = t&31) ----
    const int gb = t >> 5;        // valid when t < 256
    const int gu = t & 31;
    float creg = 0.f;
    if (t < 256) creg = c0[(size_t)(b0g + gb) * HID + u0 + gu];

    __syncthreads();

    const uint32_t hnew_base = (uint32_t)__cvta_generic_to_shared(Hnew);
    const ulonglong2* Hb = (const ulonglong2*)(Hsm + ks * HSK);

    for (int step = 0; step < SEQ; step++) {
        const int par = step & 1;

        // prefetch xw for gate threads (consumed after GEMV)
        float xvi, xvf, xvg, xvo;
        if (t < 256) {
            const float* xwp = g_xw + ((size_t)step * BATCH + b0g + gb) * GH + u0 + gu;
            xvi = xwp[0];
            xvf = xwp[256];
            xvg = xwp[512];
            xvo = xwp[768];
        }

        // ---- GEMV: 8 batches x 64-float K slice, W in regs, H broadcast ----
        ull acc[8];
        #pragma unroll
        for (int b = 0; b < 8; b++) acc[b] = 0ull;
        #pragma unroll
        for (int kk = 0; kk < 16; kk++) {
            #pragma unroll
            for (int b = 0; b < 8; b++) {
                ulonglong2 hv = Hb[b * 16 + kk];
                FMA2(acc[b], w[2 * kk], hv.x);
                FMA2(acc[b], w[2 * kk + 1], hv.y);
            }
        }
        // reduce across the 4 ks lanes (adjacent) and write Lsm
        float s0 = hsum2(acc[2 * ks]);       // place each lane's 2 target batches
        float s1 = hsum2(acc[2 * ks + 1]);
        float p[8];
        #pragma unroll
        for (int b = 0; b < 8; b++) p[b] = hsum2(acc[b]);
        #pragma unroll
        for (int b = 0; b < 8; b++) {
            p[b] += __shfl_xor_sync(0xffffffffu, p[b], 1);
            p[b] += __shfl_xor_sync(0xffffffffu, p[b], 2);
        }
        (void)s0; (void)s1;
        Lsm[(2 * ks) * LST + r]     = p[2 * ks];
        Lsm[(2 * ks + 1) * LST + r] = p[2 * ks + 1];
        __syncthreads();

        // ---- gate update (t < 256) ----
        if (t < 256) {
            const float* Lb = Lsm + gb * LST;
            float iv = Lb[gu]       + xvi;
            float fv = Lb[32 + gu]  + xvf;
            float gv = Lb[64 + gu]  + xvg;
            float ov = Lb[96 + gu]  + xvo;
            float ig = 1.f / (1.f + __expf(-iv));
            float fg = 1.f / (1.f + __expf(-fv));
            float gg = tanhf(gv);
            float og = 1.f / (1.f + __expf(-ov));
            float cc = fg * creg + ig * gg;
            creg = cc;
            float hh = og * tanhf(cc);
            int ug = u0 + gu;                       // global unit
            Hnew[par * 256 + (gb << 5) + gu] = hh;  // publish for peers
            Hsm[(ug >> 6) * HSK + gb * 64 + (ug & 63)] = hh;  // own column
            g_hs[((size_t)step * BATCH + b0g + gb) * HID + ug] = hh;
        }

        // ---- single cluster barrier: everyone published ----
        asm volatile("barrier.cluster.arrive.aligned;" ::: "memory");
        asm volatile("barrier.cluster.wait.aligned;"   ::: "memory");

        // ---- pull 7 peers' slices from their Hnew[par] into Hsm ----
        if (t < 448 && step < SEQ - 1) {
            int p7  = t >> 6;                 // 0..6
            int rem = t & 63;
            int b   = rem >> 3, q = rem & 7;
            int peer = p7 + (p7 >= myrank ? 1 : 0);
            uint32_t laddr = hnew_base + ((par * 256 + (b << 5) + (q << 2)) << 2);
            uint32_t raddr;
            asm("mapa.shared::cluster.u32 %0, %1, %2;"
                : "=r"(raddr) : "r"(laddr), "r"(peer));
            float vx, vy, vz, vw;
            asm volatile("ld.shared::cluster.v4.f32 {%0,%1,%2,%3}, [%4];"
                         : "=f"(vx), "=f"(vy), "=f"(vz), "=f"(vw)
                         : "r"(raddr));
            int ug = (peer << 5) + (q << 2);
            *(float4*)(Hsm + (ug >> 6) * HSK + b * 64 + (ug & 63)) =
                make_float4(vx, vy, vz, vw);
        }
        __syncthreads();
    }
}

// =============================================================
// Kernel C: out[m][o] = sum_h hs[m][h]*W_out[o][h] + b_out[o]
// M=262144, N=64, K=256. Tile 64x64, thread 4x4, f32x2 over K.
// =============================================================
__global__ void __launch_bounds__(256) k_gemm_out(const float* __restrict__ Wout,
                                                  const float* __restrict__ bout,
                                                  float* __restrict__ out)
{
    extern __shared__ ulonglong2 smC[];
    ulonglong2* Hs = smC;            // 64 x 19
    ulonglong2* Ws = smC + 64 * 19;  // 64 x 19

    const int t  = threadIdx.x;
    const int m0 = blockIdx.x * 64;
    const int tx = t & 15, ty = t >> 4;

    ull acc[4][4];
    #pragma unroll
    for (int i = 0; i < 4; i++)
        #pragma unroll
        for (int j = 0; j < 4; j++) acc[i][j] = 0ull;

    const ulonglong2* hs4 = (const ulonglong2*)g_hs;
    const ulonglong2* wo4 = (const ulonglong2*)Wout;

    for (int kc = 0; kc < 4; kc++) {
        __syncthreads();
        #pragma unroll
        for (int idx = t; idx < 64 * 16; idx += 256) {
            int rr = idx >> 4, c = idx & 15;
            Hs[rr * 19 + c] = hs4[(size_t)(m0 + rr) * 64 + kc * 16 + c];
            Ws[rr * 19 + c] = wo4[(size_t)rr * 64 + kc * 16 + c];
        }
        __syncthreads();
        #pragma unroll
        for (int k4 = 0; k4 < 16; k4++) {
            ulonglong2 a2[4];
            #pragma unroll
            for (int i = 0; i < 4; i++) a2[i] = Hs[(ty + 16 * i) * 19 + k4];
            #pragma unroll
            for (int j = 0; j < 4; j++) {
                ulonglong2 b2 = Ws[(tx + 16 * j) * 19 + k4];
                #pragma unroll
                for (int i = 0; i < 4; i++) {
                    FMA2(acc[i][j], a2[i].x, b2.x);
                    FMA2(acc[i][j], a2[i].y, b2.y);
                }
            }
        }
    }
    #pragma unroll
    for (int i = 0; i < 4; i++) {
        size_t m = (size_t)(m0 + ty + 16 * i);
        #pragma unroll
        for (int j = 0; j < 4; j++) {
            int n = tx + 16 * j;
            out[m * OUTD + n] = hsum2(acc[i][j]) + __ldg(&bout[n]);
        }
    }
}

// =============================================================
extern "C" void kernel_launch(void* const* d_in, const int* in_sizes, int n_in,
                              void* d_out, int out_size)
{
    (void)in_sizes; (void)n_in; (void)out_size;
    const float* x    = (const float*)d_in[0];
    const float* h0   = (const float*)d_in[1];
    const float* c0   = (const float*)d_in[2];
    const float* Wih  = (const float*)d_in[3];
    const float* Whh  = (const float*)d_in[4];
    const float* b    = (const float*)d_in[5];
    const float* Wout = (const float*)d_in[6];
    const float* bout = (const float*)d_in[7];
    float* out = (float*)d_out;

    const int smA = (64 + 128) * 19 * 16;   // 58368 B
    const int smC = (64 + 64) * 19 * 16;    // 38912 B

    cudaFuncSetAttribute(k_gemm_xw,  cudaFuncAttributeMaxDynamicSharedMemorySize, smA);
    cudaFuncSetAttribute(k_gemm_out, cudaFuncAttributeMaxDynamicSharedMemorySize, smC);

    dim3 gridA((SEQ * BATCH) / 64, GH / 128);
    k_gemm_xw<<<gridA, 256, smA>>>(x, Wih, b);

    k_lstm<<<128, 512>>>(h0, c0, Whh);

    k_gemm_out<<<(SEQ * BATCH) / 64, 256, smC>>>(Wout, bout, out);
}

// round 5
// speedup vs baseline: 1.1947x; 1.1947x over previous
#include <cuda_runtime.h>
#include <cstdint>

#define SEQ   2048
#define BATCH 128
#define INP   64
#define HID   256
#define GH    1024   // 4*HID
#define OUTD  64

typedef unsigned long long ull;

// packed 2xfp32 FMA (B300: FFMA-3reg is half rate; f32x2 restores full rate)
#define FMA2(d, a, b) asm("fma.rn.f32x2 %0, %1, %2, %0;" : "+l"(d) : "l"(a), "l"(b))

__device__ __forceinline__ float hsum2(ull v) {
    float2 f = *(float2*)&v;
    return f.x + f.y;
}

// ---------------- scratch (static device arrays; no cudaMalloc) --------
__device__ float g_xw[(size_t)SEQ * BATCH * GH];   // x @ W_ih^T + b
__device__ float g_hs[(size_t)SEQ * BATCH * HID];  // h history

// =============================================================
// Kernel A (proven R1 form, ~940us): xw = x @ W_ih^T + b
// =============================================================
__global__ void __launch_bounds__(256) k_gemm_xw(const float* __restrict__ x,
                                                 const float* __restrict__ Wih,
                                                 const float* __restrict__ bias)
{
    extern __shared__ float4 smA[];
    float4* Xs = smA;            // 64 rows x 19
    float4* Ws = smA + 64 * 19;  // 128 rows x 19

    const int t  = threadIdx.x;
    const int m0 = blockIdx.x * 64;
    const int n0 = blockIdx.y * 128;

    const float4* x4 = (const float4*)x;
    const float4* w4 = (const float4*)Wih;

    #pragma unroll
    for (int idx = t; idx < 64 * 16; idx += 256) {
        int r = idx >> 4, c = idx & 15;
        Xs[r * 19 + c] = x4[(size_t)(m0 + r) * 16 + c];
    }
    #pragma unroll
    for (int idx = t; idx < 128 * 16; idx += 256) {
        int r = idx >> 4, c = idx & 15;
        Ws[r * 19 + c] = w4[(size_t)(n0 + r) * 16 + c];
    }
    __syncthreads();

    const int tx = t & 15, ty = t >> 4;
    float acc[4][8];
    #pragma unroll
    for (int i = 0; i < 4; i++)
        #pragma unroll
        for (int j = 0; j < 8; j++) acc[i][j] = 0.f;

    #pragma unroll
    for (int k4 = 0; k4 < 16; k4++) {
        float4 a[4], bv[8];
        #pragma unroll
        for (int i = 0; i < 4; i++) a[i] = Xs[(ty + 16 * i) * 19 + k4];
        #pragma unroll
        for (int j = 0; j < 8; j++) bv[j] = Ws[(tx + 16 * j) * 19 + k4];
        #pragma unroll
        for (int i = 0; i < 4; i++)
            #pragma unroll
            for (int j = 0; j < 8; j++)
                acc[i][j] += a[i].x * bv[j].x + a[i].y * bv[j].y +
                             a[i].z * bv[j].z + a[i].w * bv[j].w;
    }
    #pragma unroll
    for (int i = 0; i < 4; i++) {
        int m = m0 + ty + 16 * i;
        #pragma unroll
        for (int j = 0; j < 8; j++) {
            int n = n0 + tx + 16 * j;
            g_xw[(size_t)m * GH + n] = acc[i][j] + __ldg(&bias[n]);
        }
    }
}

// =============================================================
// Kernel B: persistent LSTM scan. 128 CTAs = 16 batch-groups(8 b) x
// 8 unit-groups(32 u). Cluster of 8 per batch-group; h via DSMEM.
// 512 threads: thread = (row-pair, K-quarter ks, batch-half bp).
// W in SMEM (skewed layout, conflict-free), f32x2 FMAs,
// single parity-buffered cluster barrier per step.
// =============================================================
#define WS   268   // W row stride (floats) = 3*KSK + 64 exactly (FIX: was 264)
#define KSK  68    // ks-slice skew (floats) inside a W row / H batch slice
#define HSK  548   // H ks-slice stride (floats) = 8*68 + 4
#define LST  132   // L batch stride (floats)

#define SM_W   0
#define SM_H   (128 * WS)              // 34304
#define SM_L   (SM_H + 4 * HSK)        // +2192 = 36496
#define SM_HN  (SM_L + 8 * LST)        // +1056 = 37552
#define SM_TOT (SM_HN + 2 * 256)       // +512  = 38064 floats = 152256 B

__global__ void __launch_bounds__(512, 1) __cluster_dims__(8, 1, 1)
k_lstm(const float* __restrict__ h0, const float* __restrict__ c0,
       const float* __restrict__ Whh)
{
    extern __shared__ float smR[];
    float* Wsm  = smR + SM_W;   // [row r 0..127][ks*68 + k(0..63)]
    float* Hsm  = smR + SM_H;   // [ks 0..3][b*68 + k(0..63)]
    float* Lsm  = smR + SM_L;   // [b 0..7][row 0..127]
    float* Hnew = smR + SM_HN;  // [parity][b*32 + u]  published slice

    const int t      = threadIdx.x;
    const int bgrp   = blockIdx.x >> 3;     // 0..15
    const int myrank = blockIdx.x & 7;      // cluster rank
    const int b0g    = bgrp << 3;           // global batch base (8 batches)
    const int u0     = myrank << 5;         // global unit base (32 units)

    const int w    = t >> 5, lane = t & 31;
    const int rp   = (w << 2) + (lane >> 3);     // row pair 0..63
    const int ks   = (lane >> 1) & 3;            // K quarter
    const int bp   = lane & 1;                   // batch half

    // ---- load W_hh slice into SMEM once (skewed layout) ----
    for (int idx = t; idx < 128 * 64; idx += 512) {
        int r = idx >> 6, c4 = idx & 63;             // c4 = float4 index in row
        int grow = ((r >> 5) << 8) + u0 + (r & 31);  // global gate row
        float4 v = ((const float4*)Whh)[(size_t)grow * 64 + c4];
        int kss = c4 >> 4, kk = (c4 & 15) << 2;
        *(float4*)(Wsm + r * WS + kss * KSK + kk) = v;
    }
    // ---- init Hsm from h0 ----
    {
        int b = t >> 6, c4 = t & 63;                 // 512 -> 8b x 64 f4
        float4 v = ((const float4*)h0)[(size_t)(b0g + b) * 64 + c4];
        int kss = c4 >> 4, kk = (c4 & 15) << 2;
        *(float4*)(Hsm + kss * HSK + b * KSK + kk) = v;
    }

    // ---- gate-thread state (t < 256): b = t>>5, u = t&31 ----
    const int gb = t >> 5;
    const int gu = t & 31;
    float creg = 0.f;
    if (t < 256) creg = c0[(size_t)(b0g + gb) * HID + u0 + gu];

    __syncthreads();

    const uint32_t hnew_base = (uint32_t)__cvta_generic_to_shared(Hnew);
    const float* Wp0 = Wsm + (rp * 2 + 0) * WS + ks * KSK;
    const float* Wp1 = Wsm + (rp * 2 + 1) * WS + ks * KSK;
    const float* Hp  = Hsm + ks * HSK + (bp << 2) * KSK;

    #pragma unroll 1
    for (int step = 0; step < SEQ; step++) {
        const int par = step & 1;

        // prefetch xw for gate threads (consumed after GEMV)
        float xvi, xvf, xvg, xvo;
        if (t < 256) {
            const float* xwp = g_xw + ((size_t)step * BATCH + b0g + gb) * GH + u0 + gu;
            xvi = xwp[0];
            xvf = xwp[256];
            xvg = xwp[512];
            xvo = xwp[768];
        }

        // ---- GEMV: 2 rows x 4 batches x 64-K-quarter ----
        ull acc00 = 0, acc01 = 0, acc02 = 0, acc03 = 0;
        ull acc10 = 0, acc11 = 0, acc12 = 0, acc13 = 0;
        #pragma unroll
        for (int k4 = 0; k4 < 16; k4++) {
            ulonglong2 w0 = *(const ulonglong2*)(Wp0 + k4 * 4);
            ulonglong2 w1 = *(const ulonglong2*)(Wp1 + k4 * 4);
            ulonglong2 hv;
            hv = *(const ulonglong2*)(Hp + 0 * KSK + k4 * 4);
            FMA2(acc00, w0.x, hv.x); FMA2(acc00, w0.y, hv.y);
            FMA2(acc10, w1.x, hv.x); FMA2(acc10, w1.y, hv.y);
            hv = *(const ulonglong2*)(Hp + 1 * KSK + k4 * 4);
            FMA2(acc01, w0.x, hv.x); FMA2(acc01, w0.y, hv.y);
            FMA2(acc11, w1.x, hv.x); FMA2(acc11, w1.y, hv.y);
            hv = *(const ulonglong2*)(Hp + 2 * KSK + k4 * 4);
            FMA2(acc02, w0.x, hv.x); FMA2(acc02, w0.y, hv.y);
            FMA2(acc12, w1.x, hv.x); FMA2(acc12, w1.y, hv.y);
            hv = *(const ulonglong2*)(Hp + 3 * KSK + k4 * 4);
            FMA2(acc03, w0.x, hv.x); FMA2(acc03, w0.y, hv.y);
            FMA2(acc13, w1.x, hv.x); FMA2(acc13, w1.y, hv.y);
        }
        // reduce over the 4 ks lanes (lane bits 1-2) and store to Lsm
        {
            const int r0 = rp * 2, bb = bp << 2;
            float v;
            v = hsum2(acc00); v += __shfl_xor_sync(~0u, v, 2); v += __shfl_xor_sync(~0u, v, 4);
            if (ks == 0) Lsm[(bb + 0) * LST + r0] = v;
            v = hsum2(acc01); v += __shfl_xor_sync(~0u, v, 2); v += __shfl_xor_sync(~0u, v, 4);
            if (ks == 0) Lsm[(bb + 1) * LST + r0] = v;
            v = hsum2(acc02); v += __shfl_xor_sync(~0u, v, 2); v += __shfl_xor_sync(~0u, v, 4);
            if (ks == 0) Lsm[(bb + 2) * LST + r0] = v;
            v = hsum2(acc03); v += __shfl_xor_sync(~0u, v, 2); v += __shfl_xor_sync(~0u, v, 4);
            if (ks == 0) Lsm[(bb + 3) * LST + r0] = v;
            v = hsum2(acc10); v += __shfl_xor_sync(~0u, v, 2); v += __shfl_xor_sync(~0u, v, 4);
            if (ks == 0) Lsm[(bb + 0) * LST + r0 + 1] = v;
            v = hsum2(acc11); v += __shfl_xor_sync(~0u, v, 2); v += __shfl_xor_sync(~0u, v, 4);
            if (ks == 0) Lsm[(bb + 1) * LST + r0 + 1] = v;
            v = hsum2(acc12); v += __shfl_xor_sync(~0u, v, 2); v += __shfl_xor_sync(~0u, v, 4);
            if (ks == 0) Lsm[(bb + 2) * LST + r0 + 1] = v;
            v = hsum2(acc13); v += __shfl_xor_sync(~0u, v, 2); v += __shfl_xor_sync(~0u, v, 4);
            if (ks == 0) Lsm[(bb + 3) * LST + r0 + 1] = v;
        }
        __syncthreads();

        // ---- gate update (t < 256) ----
        if (t < 256) {
            const float* Lb = Lsm + gb * LST;
            float iv = Lb[gu]      + xvi;
            float fv = Lb[32 + gu] + xvf;
            float gv = Lb[64 + gu] + xvg;
            float ov = Lb[96 + gu] + xvo;
            float ig = 1.f / (1.f + __expf(-iv));
            float fg = 1.f / (1.f + __expf(-fv));
            float gg = tanhf(gv);
            float og = 1.f / (1.f + __expf(-ov));
            float cc = fg * creg + ig * gg;
            creg = cc;
            float hh = og * tanhf(cc);
            int ug = u0 + gu;                          // global unit
            Hnew[par * 256 + (gb << 5) + gu] = hh;     // publish for peers
            Hsm[(ug >> 6) * HSK + gb * KSK + (ug & 63)] = hh;  // own column
            g_hs[((size_t)step * BATCH + b0g + gb) * HID + ug] = hh;
        }

        // ---- single cluster barrier (release/acquire) ----
        asm volatile("barrier.cluster.arrive.aligned;" ::: "memory");
        asm volatile("barrier.cluster.wait.aligned;"   ::: "memory");

        // ---- pull 7 peers' h slices from their Hnew[par] into my Hsm ----
        if (t < 448 && step < SEQ - 1) {
            int p7  = t >> 6;                 // 0..6
            int rem = t & 63;
            int b   = rem >> 3, q = rem & 7;
            int peer = p7 + (p7 >= myrank ? 1 : 0);
            uint32_t laddr = hnew_base + ((par * 256 + (b << 5) + (q << 2)) << 2);
            uint32_t raddr;
            asm("mapa.shared::cluster.u32 %0, %1, %2;"
                : "=r"(raddr) : "r"(laddr), "r"(peer));
            float vx, vy, vz, vw;
            asm volatile("ld.shared::cluster.v4.f32 {%0,%1,%2,%3}, [%4];"
                         : "=f"(vx), "=f"(vy), "=f"(vz), "=f"(vw)
                         : "r"(raddr));
            int ug = (peer << 5) + (q << 2);
            *(float4*)(Hsm + (ug >> 6) * HSK + b * KSK + (ug & 63)) =
                make_float4(vx, vy, vz, vw);
        }
        __syncthreads();
    }
}

// =============================================================
// Kernel C: out = hs @ W_out^T + b_out. M=262144, N=64, K=256.
// =============================================================
__global__ void __launch_bounds__(256) k_gemm_out(const float* __restrict__ Wout,
                                                  const float* __restrict__ bout,
                                                  float* __restrict__ out)
{
    extern __shared__ ulonglong2 smC[];
    ulonglong2* Hs = smC;            // 64 x 19
    ulonglong2* Ws = smC + 64 * 19;  // 64 x 19

    const int t  = threadIdx.x;
    const int m0 = blockIdx.x * 64;
    const int tx = t & 15, ty = t >> 4;

    ull acc[4][4];
    #pragma unroll
    for (int i = 0; i < 4; i++)
        #pragma unroll
        for (int j = 0; j < 4; j++) acc[i][j] = 0ull;

    const ulonglong2* hs4 = (const ulonglong2*)g_hs;
    const ulonglong2* wo4 = (const ulonglong2*)Wout;

    for (int kc = 0; kc < 4; kc++) {
        __syncthreads();
        #pragma unroll
        for (int idx = t; idx < 64 * 16; idx += 256) {
            int rr = idx >> 4, c = idx & 15;
            Hs[rr * 19 + c] = hs4[(size_t)(m0 + rr) * 64 + kc * 16 + c];
            Ws[rr * 19 + c] = wo4[(size_t)rr * 64 + kc * 16 + c];
        }
        __syncthreads();
        #pragma unroll
        for (int k4 = 0; k4 < 16; k4++) {
            ulonglong2 a2[4];
            #pragma unroll
            for (int i = 0; i < 4; i++) a2[i] = Hs[(ty + 16 * i) * 19 + k4];
            #pragma unroll
            for (int j = 0; j < 4; j++) {
                ulonglong2 b2 = Ws[(tx + 16 * j) * 19 + k4];
                #pragma unroll
                for (int i = 0; i < 4; i++) {
                    FMA2(acc[i][j], a2[i].x, b2.x);
                    FMA2(acc[i][j], a2[i].y, b2.y);
                }
            }
        }
    }
    #pragma unroll
    for (int i = 0; i < 4; i++) {
        size_t m = (size_t)(m0 + ty + 16 * i);
        #pragma unroll
        for (int j = 0; j < 4; j++) {
            int n = tx + 16 * j;
            out[m * OUTD + n] = hsum2(acc[i][j]) + __ldg(&bout[n]);
        }
    }
}

// =============================================================
extern "C" void kernel_launch(void* const* d_in, const int* in_sizes, int n_in,
                              void* d_out, int out_size)
{
    (void)in_sizes; (void)n_in; (void)out_size;
    const float* x    = (const float*)d_in[0];
    const float* h0   = (const float*)d_in[1];
    const float* c0   = (const float*)d_in[2];
    const float* Wih  = (const float*)d_in[3];
    const float* Whh  = (const float*)d_in[4];
    const float* b    = (const float*)d_in[5];
    const float* Wout = (const float*)d_in[6];
    const float* bout = (const float*)d_in[7];
    float* out = (float*)d_out;

    const int smA = (64 + 128) * 19 * 16;   // 58368 B
    const int smB = SM_TOT * 4;             // 152256 B
    const int smC = (64 + 64) * 19 * 16;    // 38912 B

    cudaFuncSetAttribute(k_gemm_xw,  cudaFuncAttributeMaxDynamicSharedMemorySize, smA);
    cudaFuncSetAttribute(k_lstm,     cudaFuncAttributeMaxDynamicSharedMemorySize, smB);
    cudaFuncSetAttribute(k_gemm_out, cudaFuncAttributeMaxDynamicSharedMemorySize, smC);

    dim3 gridA((SEQ * BATCH) / 64, GH / 128);
    k_gemm_xw<<<gridA, 256, smA>>>(x, Wih, b);

    k_lstm<<<128, 512, smB>>>(h0, c0, Whh);

    k_gemm_out<<<(SEQ * BATCH) / 64, 256, smC>>>(Wout, bout, out);
}

// round 6
// speedup vs baseline: 1.6012x; 1.3402x over previous
#include <cuda_runtime.h>
#include <cstdint>

#define SEQ   2048
#define BATCH 128
#define INP   64
#define HID   256
#define GH    1024   // 4*HID
#define OUTD  64
#define NBG   16     // batch groups (8 batches each)
#define NUG   8      // unit groups  (32 units each)

typedef unsigned long long ull;

// packed 2xfp32 FMA (B300: FFMA-3reg is half rate; f32x2 restores full rate)
#define FMA2(d, a, b) asm("fma.rn.f32x2 %0, %1, %2, %0;" : "+l"(d) : "l"(a), "l"(b))

__device__ __forceinline__ float hsum2(ull v) {
    float2 f = *(float2*)&v;
    return f.x + f.y;
}

// ---------------- scratch (static device arrays; no cudaMalloc) --------
__device__ float g_xw[(size_t)SEQ * BATCH * GH];   // x @ W_ih^T + b
__device__ float g_hs[(size_t)SEQ * BATCH * HID];  // h history (streamed)
__device__ float g_hx[2][BATCH * HID];             // hot h exchange (L2)
__device__ unsigned g_cnt2[NBG * 32];              // per-bgroup counters (128B apart)
__device__ volatile unsigned g_gen2[NBG * 32];     // per-bgroup generations

// =============================================================
// Kernel A (proven, ~940us): xw = x @ W_ih^T + b
// =============================================================
__global__ void __launch_bounds__(256) k_gemm_xw(const float* __restrict__ x,
                                                 const float* __restrict__ Wih,
                                                 const float* __restrict__ bias)
{
    extern __shared__ float4 smA[];
    float4* Xs = smA;            // 64 rows x 19
    float4* Ws = smA + 64 * 19;  // 128 rows x 19

    const int t  = threadIdx.x;
    const int m0 = blockIdx.x * 64;
    const int n0 = blockIdx.y * 128;

    const float4* x4 = (const float4*)x;
    const float4* w4 = (const float4*)Wih;

    #pragma unroll
    for (int idx = t; idx < 64 * 16; idx += 256) {
        int r = idx >> 4, c = idx & 15;
        Xs[r * 19 + c] = x4[(size_t)(m0 + r) * 16 + c];
    }
    #pragma unroll
    for (int idx = t; idx < 128 * 16; idx += 256) {
        int r = idx >> 4, c = idx & 15;
        Ws[r * 19 + c] = w4[(size_t)(n0 + r) * 16 + c];
    }
    __syncthreads();

    const int tx = t & 15, ty = t >> 4;
    float acc[4][8];
    #pragma unroll
    for (int i = 0; i < 4; i++)
        #pragma unroll
        for (int j = 0; j < 8; j++) acc[i][j] = 0.f;

    #pragma unroll
    for (int k4 = 0; k4 < 16; k4++) {
        float4 a[4], bv[8];
        #pragma unroll
        for (int i = 0; i < 4; i++) a[i] = Xs[(ty + 16 * i) * 19 + k4];
        #pragma unroll
        for (int j = 0; j < 8; j++) bv[j] = Ws[(tx + 16 * j) * 19 + k4];
        #pragma unroll
        for (int i = 0; i < 4; i++)
            #pragma unroll
            for (int j = 0; j < 8; j++)
                acc[i][j] += a[i].x * bv[j].x + a[i].y * bv[j].y +
                             a[i].z * bv[j].z + a[i].w * bv[j].w;
    }
    #pragma unroll
    for (int i = 0; i < 4; i++) {
        int m = m0 + ty + 16 * i;
        #pragma unroll
        for (int j = 0; j < 8; j++) {
            int n = n0 + tx + 16 * j;
            g_xw[(size_t)m * GH + n] = acc[i][j] + __ldg(&bias[n]);
        }
    }
}

// =============================================================
// Kernel B: persistent LSTM scan, NO clusters.
// 128 CTAs = 16 bgroups(8 b) x 8 ugroups(32 u / 128 gate rows).
// Sync: per-bgroup (8 CTAs) atomic counter + generation in L2.
// Exchange: compact double-buffered g_hx in L2.
// GEMV: R5's proven 512-thread f32x2 layout (W smem 137KB).
// xw prefetched one step ahead (hidden behind the barrier).
// =============================================================
#define WS   268   // W row stride (floats) = 3*KSK + 64
#define KSK  68    // ks-slice skew
#define HSK  548   // H ks-slice stride = 8*68 + 4
#define LST  132   // L batch stride

#define SM_W   0
#define SM_H   (128 * WS)              // 34304
#define SM_L   (SM_H + 4 * HSK)        // 36496
#define SM_TOT (SM_L + 8 * LST)        // 37552 floats = 150208 B

__global__ void __launch_bounds__(512, 1)
k_lstm(const float* __restrict__ h0, const float* __restrict__ c0,
       const float* __restrict__ Whh)
{
    extern __shared__ float smR[];
    float* Wsm = smR + SM_W;   // [row r 0..127][ks*68 + k(0..63)]
    float* Hsm = smR + SM_H;   // [ks 0..3][b*68 + k(0..63)]
    float* Lsm = smR + SM_L;   // [b 0..7][row 0..127]

    const int t     = threadIdx.x;
    const int bgrp  = blockIdx.x >> 3;      // 0..15
    const int urank = blockIdx.x & 7;       // 0..7
    const int b0g   = bgrp << 3;            // global batch base
    const int u0    = urank << 5;           // global unit base

    const int w    = t >> 5, lane = t & 31;
    const int rp   = (w << 2) + (lane >> 3);     // row pair 0..63
    const int ks   = (lane >> 1) & 3;            // K quarter
    const int bp   = lane & 1;                   // batch half

    // ---- load W_hh slice into SMEM once (R5-proven layout) ----
    for (int idx = t; idx < 128 * 64; idx += 512) {
        int r = idx >> 6, c4 = idx & 63;
        int grow = ((r >> 5) << 8) + u0 + (r & 31);
        float4 v = ((const float4*)Whh)[(size_t)grow * 64 + c4];
        int kss = c4 >> 4, kk = (c4 & 15) << 2;
        *(float4*)(Wsm + r * WS + kss * KSK + kk) = v;
    }
    // ---- init Hsm from h0 ----
    {
        int b = t >> 6, c4 = t & 63;
        float4 v = ((const float4*)h0)[(size_t)(b0g + b) * 64 + c4];
        int kss = c4 >> 4, kk = (c4 & 15) << 2;
        *(float4*)(Hsm + kss * HSK + b * KSK + kk) = v;
    }

    // ---- gate-thread state (t < 256) ----
    const int gb = t >> 5;
    const int gu = t & 31;
    float creg = 0.f;
    if (t < 256) creg = c0[(size_t)(b0g + gb) * HID + u0 + gu];

    __syncthreads();

    const float* Wp0 = Wsm + (rp * 2 + 0) * WS + ks * KSK;
    const float* Wp1 = Wsm + (rp * 2 + 1) * WS + ks * KSK;
    const float* Hp  = Hsm + ks * HSK + (bp << 2) * KSK;

    // prefetch xw for step 0
    float xvi = 0.f, xvf = 0.f, xvg = 0.f, xvo = 0.f;
    if (t < 256) {
        const float* xwp = g_xw + ((size_t)(b0g + gb)) * GH + u0 + gu;
        xvi = xwp[0];
        xvf = xwp[256];
        xvg = xwp[512];
        xvo = xwp[768];
    }

    unsigned* cntp = &g_cnt2[bgrp * 32];
    volatile unsigned* genp = &g_gen2[bgrp * 32];

    #pragma unroll 1
    for (int step = 0; step < SEQ; step++) {
        const int par = step & 1;

        // ---- GEMV: 2 rows x 4 batches x 64-K-quarter (R5-proven) ----
        ull acc00 = 0, acc01 = 0, acc02 = 0, acc03 = 0;
        ull acc10 = 0, acc11 = 0, acc12 = 0, acc13 = 0;
        #pragma unroll
        for (int k4 = 0; k4 < 16; k4++) {
            ulonglong2 w0 = *(const ulonglong2*)(Wp0 + k4 * 4);
            ulonglong2 w1 = *(const ulonglong2*)(Wp1 + k4 * 4);
            ulonglong2 hv;
            hv = *(const ulonglong2*)(Hp + 0 * KSK + k4 * 4);
            FMA2(acc00, w0.x, hv.x); FMA2(acc00, w0.y, hv.y);
            FMA2(acc10, w1.x, hv.x); FMA2(acc10, w1.y, hv.y);
            hv = *(const ulonglong2*)(Hp + 1 * KSK + k4 * 4);
            FMA2(acc01, w0.x, hv.x); FMA2(acc01, w0.y, hv.y);
            FMA2(acc11, w1.x, hv.x); FMA2(acc11, w1.y, hv.y);
            hv = *(const ulonglong2*)(Hp + 2 * KSK + k4 * 4);
            FMA2(acc02, w0.x, hv.x); FMA2(acc02, w0.y, hv.y);
            FMA2(acc12, w1.x, hv.x); FMA2(acc12, w1.y, hv.y);
            hv = *(const ulonglong2*)(Hp + 3 * KSK + k4 * 4);
            FMA2(acc03, w0.x, hv.x); FMA2(acc03, w0.y, hv.y);
            FMA2(acc13, w1.x, hv.x); FMA2(acc13, w1.y, hv.y);
        }
        {
            const int r0 = rp * 2, bb = bp << 2;
            float v;
            v = hsum2(acc00); v += __shfl_xor_sync(~0u, v, 2); v += __shfl_xor_sync(~0u, v, 4);
            if (ks == 0) Lsm[(bb + 0) * LST + r0] = v;
            v = hsum2(acc01); v += __shfl_xor_sync(~0u, v, 2); v += __shfl_xor_sync(~0u, v, 4);
            if (ks == 0) Lsm[(bb + 1) * LST + r0] = v;
            v = hsum2(acc02); v += __shfl_xor_sync(~0u, v, 2); v += __shfl_xor_sync(~0u, v, 4);
            if (ks == 0) Lsm[(bb + 2) * LST + r0] = v;
            v = hsum2(acc03); v += __shfl_xor_sync(~0u, v, 2); v += __shfl_xor_sync(~0u, v, 4);
            if (ks == 0) Lsm[(bb + 3) * LST + r0] = v;
            v = hsum2(acc10); v += __shfl_xor_sync(~0u, v, 2); v += __shfl_xor_sync(~0u, v, 4);
            if (ks == 0) Lsm[(bb + 0) * LST + r0 + 1] = v;
            v = hsum2(acc11); v += __shfl_xor_sync(~0u, v, 2); v += __shfl_xor_sync(~0u, v, 4);
            if (ks == 0) Lsm[(bb + 1) * LST + r0 + 1] = v;
            v = hsum2(acc12); v += __shfl_xor_sync(~0u, v, 2); v += __shfl_xor_sync(~0u, v, 4);
            if (ks == 0) Lsm[(bb + 2) * LST + r0 + 1] = v;
            v = hsum2(acc13); v += __shfl_xor_sync(~0u, v, 2); v += __shfl_xor_sync(~0u, v, 4);
            if (ks == 0) Lsm[(bb + 3) * LST + r0 + 1] = v;
        }
        __syncthreads();

        // ---- gate update (t < 256) ----
        if (t < 256) {
            const float* Lb = Lsm + gb * LST;
            float iv = Lb[gu]      + xvi;
            float fv = Lb[32 + gu] + xvf;
            float gv = Lb[64 + gu] + xvg;
            float ov = Lb[96 + gu] + xvo;
            float ig = 1.f / (1.f + __expf(-iv));
            float fg = 1.f / (1.f + __expf(-fv));
            float gg = tanhf(gv);
            float og = 1.f / (1.f + __expf(-ov));
            float cc = fg * creg + ig * gg;
            creg = cc;
            float hh = og * tanhf(cc);
            int ug = u0 + gu;
            g_hx[par][(b0g + gb) * HID + ug] = hh;                  // hot exchange
            __stcs(&g_hs[((size_t)step * BATCH + b0g + gb) * HID + ug], hh); // history
            // prefetch xw for next step (hidden behind barrier+spin)
            if (step + 1 < SEQ) {
                const float* xwp = g_xw + ((size_t)(step + 1) * BATCH + b0g + gb) * GH + u0 + gu;
                xvi = xwp[0];
                xvf = xwp[256];
                xvg = xwp[512];
                xvo = xwp[768];
            }
        }
        __threadfence();
        __syncthreads();

        // ---- per-bgroup barrier (8 CTAs), t==0 only ----
        if (t == 0) {
            unsigned cur = *genp;
            if (atomicAdd(cntp, 1u) == (unsigned)(NUG - 1)) {
                atomicExch(cntp, 0u);
                __threadfence();
                *genp = cur + 1u;
            } else {
                while (*genp == cur) { }
            }
            __threadfence();
        }
        __syncthreads();

        // ---- reload all 8 h slices for my 8 batches from g_hx[par] ----
        if (step < SEQ - 1) {
            int b = t >> 6, c4 = t & 63;
            float4 v = *(const float4*)&g_hx[par][(b0g + b) * HID + (c4 << 2)];
            int kss = c4 >> 4, kk = (c4 & 15) << 2;
            *(float4*)(Hsm + kss * HSK + b * KSK + kk) = v;
            __syncthreads();
        }
    }
}

// =============================================================
// Kernel C: out = hs @ W_out^T + b_out. M=262144, N=64, K=256.
// =============================================================
__global__ void __launch_bounds__(256) k_gemm_out(const float* __restrict__ Wout,
                                                  const float* __restrict__ bout,
                                                  float* __restrict__ out)
{
    extern __shared__ ulonglong2 smC[];
    ulonglong2* Hs = smC;            // 64 x 19
    ulonglong2* Ws = smC + 64 * 19;  // 64 x 19

    const int t  = threadIdx.x;
    const int m0 = blockIdx.x * 64;
    const int tx = t & 15, ty = t >> 4;

    ull acc[4][4];
    #pragma unroll
    for (int i = 0; i < 4; i++)
        #pragma unroll
        for (int j = 0; j < 4; j++) acc[i][j] = 0ull;

    const ulonglong2* hs4 = (const ulonglong2*)g_hs;
    const ulonglong2* wo4 = (const ulonglong2*)Wout;

    for (int kc = 0; kc < 4; kc++) {
        __syncthreads();
        #pragma unroll
        for (int idx = t; idx < 64 * 16; idx += 256) {
            int rr = idx >> 4, c = idx & 15;
            Hs[rr * 19 + c] = hs4[(size_t)(m0 + rr) * 64 + kc * 16 + c];
            Ws[rr * 19 + c] = wo4[(size_t)rr * 64 + kc * 16 + c];
        }
        __syncthreads();
        #pragma unroll
        for (int k4 = 0; k4 < 16; k4++) {
            ulonglong2 a2[4];
            #pragma unroll
            for (int i = 0; i < 4; i++) a2[i] = Hs[(ty + 16 * i) * 19 + k4];
            #pragma unroll
            for (int j = 0; j < 4; j++) {
                ulonglong2 b2 = Ws[(tx + 16 * j) * 19 + k4];
                #pragma unroll
                for (int i = 0; i < 4; i++) {
                    FMA2(acc[i][j], a2[i].x, b2.x);
                    FMA2(acc[i][j], a2[i].y, b2.y);
                }
            }
        }
    }
    #pragma unroll
    for (int i = 0; i < 4; i++) {
        size_t m = (size_t)(m0 + ty + 16 * i);
        #pragma unroll
        for (int j = 0; j < 4; j++) {
            int n = tx + 16 * j;
            out[m * OUTD + n] = hsum2(acc[i][j]) + __ldg(&bout[n]);
        }
    }
}

// =============================================================
extern "C" void kernel_launch(void* const* d_in, const int* in_sizes, int n_in,
                              void* d_out, int out_size)
{
    (void)in_sizes; (void)n_in; (void)out_size;
    const float* x    = (const float*)d_in[0];
    const float* h0   = (const float*)d_in[1];
    const float* c0   = (const float*)d_in[2];
    const float* Wih  = (const float*)d_in[3];
    const float* Whh  = (const float*)d_in[4];
    const float* b    = (const float*)d_in[5];
    const float* Wout = (const float*)d_in[6];
    const float* bout = (const float*)d_in[7];
    float* out = (float*)d_out;

    const int smA = (64 + 128) * 19 * 16;   // 58368 B
    const int smB = SM_TOT * 4;             // 150208 B
    const int smC = (64 + 64) * 19 * 16;    // 38912 B

    cudaFuncSetAttribute(k_gemm_xw,  cudaFuncAttributeMaxDynamicSharedMemorySize, smA);
    cudaFuncSetAttribute(k_lstm,     cudaFuncAttributeMaxDynamicSharedMemorySize, smB);
    cudaFuncSetAttribute(k_gemm_out, cudaFuncAttributeMaxDynamicSharedMemorySize, smC);

    dim3 gridA((SEQ * BATCH) / 64, GH / 128);
    k_gemm_xw<<<gridA, 256, smA>>>(x, Wih, b);

    k_lstm<<<128, 512, smB>>>(h0, c0, Whh);

    k_gemm_out<<<(SEQ * BATCH) / 64, 256, smC>>>(Wout, bout, out);
}